// round 6
// baseline (speedup 1.0000x reference)
#include <cuda_runtime.h>

#define NN 10000
#define DD 128
#define MAXE 512
#define NV4 (NN / 4)          // 2500 float4 per adj row

__device__ float g_score[NN];

// ---------------------------------------------------------------------------
// Kernel 1: score[j] = dot(inputs[j,:], H_v)   — one warp per row
// ---------------------------------------------------------------------------
__global__ __launch_bounds__(128) void score_kernel(
    const float* __restrict__ inputs, const float* __restrict__ Hv)
{
    int row  = blockIdx.x * (blockDim.x >> 5) + (threadIdx.x >> 5);
    int lane = threadIdx.x & 31;
    if (row >= NN) return;
    const float4* ip = reinterpret_cast<const float4*>(inputs + (size_t)row * DD);
    const float4* hv = reinterpret_cast<const float4*>(Hv);
    float4 a = ip[lane];
    float4 h = hv[lane];
    float acc = a.x * h.x + a.y * h.y + a.z * h.z + a.w * h.w;
    #pragma unroll
    for (int off = 16; off > 0; off >>= 1)
        acc += __shfl_xor_sync(0xffffffffu, acc, off);
    if (lane == 0) g_score[row] = acc;
}

// ---------------------------------------------------------------------------
// Kernel 2: one CTA (128 threads) per row. 64-reg budget (8 CTAs/SM) so the
// 8 front-batched float4 loads are genuinely in flight. Ballot compaction.
// ---------------------------------------------------------------------------
__global__ __launch_bounds__(128, 8) void attn_kernel(
    const float* __restrict__ inputs,
    const float* __restrict__ adj,
    float* __restrict__ out)
{
    __shared__ alignas(16) float s_w[MAXE];
    __shared__ alignas(16) float s_part[4 * DD];
    __shared__ int   s_idx[MAXE];
    __shared__ int   s_cnt;
    __shared__ float s_red[4];

    const int row  = blockIdx.x;
    const int tid  = threadIdx.x;
    const int wid  = tid >> 5;
    const int lane = tid & 31;
    const unsigned lt = (1u << lane) - 1u;

    if (tid == 0) s_cnt = 0;
    __syncthreads();

    const float4* arow = reinterpret_cast<const float4*>(adj + (size_t)row * NN);

    // Warp-ballot compaction: one aggregated atomicAdd per warp per float4.
    auto proc = [&](float4 a, int j) {
        bool bx = a.x != 0.0f, by = a.y != 0.0f, bz = a.z != 0.0f, bw = a.w != 0.0f;
        unsigned mx = __ballot_sync(0xffffffffu, bx);
        unsigned my = __ballot_sync(0xffffffffu, by);
        unsigned mz = __ballot_sync(0xffffffffu, bz);
        unsigned mw = __ballot_sync(0xffffffffu, bw);
        if ((mx | my | mz | mw) == 0u) return;        // warp-uniform
        int cx = __popc(mx), cy = __popc(my), cz = __popc(mz), cw = __popc(mw);
        int base = 0;
        if (lane == 0) base = atomicAdd(&s_cnt, cx + cy + cz + cw);
        base = __shfl_sync(0xffffffffu, base, 0);
        if (bx) { int p = base + __popc(mx & lt);           s_idx[p] = j;     s_w[p] = a.x; }
        base += cx;
        if (by) { int p = base + __popc(my & lt);           s_idx[p] = j + 1; s_w[p] = a.y; }
        base += cy;
        if (bz) { int p = base + __popc(mz & lt);           s_idx[p] = j + 2; s_w[p] = a.z; }
        base += cz;
        if (bw) { int p = base + __popc(mw & lt);           s_idx[p] = j + 3; s_w[p] = a.w; }
    };

    // ---- Pass 1: scan, 8 float4 front-batched per iteration ----------------
    #pragma unroll
    for (int i = 0; i < 2; i++) {
        const int v0 = tid + i * 1024;
        float4 a[8];
        #pragma unroll
        for (int u = 0; u < 8; u++) a[u] = __ldcs(&arow[v0 + u * 128]);
        #pragma unroll
        for (int u = 0; u < 8; u++) proc(a[u], (v0 + u * 128) << 2);
    }
    {   // tail: v in [2048, 2500) = 452 float4
        const int v0 = 2048 + tid;
        const bool t3 = (v0 + 384) < NV4;     // tid < 68
        float4 a0 = __ldcs(&arow[v0]);
        float4 a1 = __ldcs(&arow[v0 + 128]);
        float4 a2 = __ldcs(&arow[v0 + 256]);
        float4 a3 = make_float4(0.f, 0.f, 0.f, 0.f);
        if (t3) a3 = __ldcs(&arow[v0 + 384]);
        proc(a0, v0 << 2);
        proc(a1, (v0 + 128) << 2);
        proc(a2, (v0 + 256) << 2);
        proc(a3, (v0 + 384) << 2);            // all-zero for invalid lanes; ballot-safe
    }
    __syncthreads();
    const int cnt = s_cnt;

    // ---- Pass 2a: logits (parallel score gather) ---------------------------
    for (int k = tid; k < cnt; k += 128)
        s_w[k] = s_w[k] * __ldg(&g_score[s_idx[k]]);
    __syncthreads();

    // ---- Pass 2b: softmax --------------------------------------------------
    float m = -1e30f;
    for (int k = tid; k < cnt; k += 128) m = fmaxf(m, s_w[k]);
    #pragma unroll
    for (int off = 16; off > 0; off >>= 1)
        m = fmaxf(m, __shfl_xor_sync(0xffffffffu, m, off));
    if (lane == 0) s_red[wid] = m;
    __syncthreads();
    m = fmaxf(fmaxf(s_red[0], s_red[1]), fmaxf(s_red[2], s_red[3]));
    __syncthreads();

    float s = 0.0f;
    for (int k = tid; k < cnt; k += 128) {
        float e = __expf(s_w[k] - m);
        s_w[k] = e;
        s += e;
    }
    #pragma unroll
    for (int off = 16; off > 0; off >>= 1)
        s += __shfl_xor_sync(0xffffffffu, s, off);
    if (lane == 0) s_red[wid] = s;
    __syncthreads();
    s = s_red[0] + s_red[1] + s_red[2] + s_red[3];
    const float inv = 1.0f / s;

    // ---- Pass 3: warp-split float4 gather ----------------------------------
    const float4* inp4 = reinterpret_cast<const float4*>(inputs);
    float4 acc = make_float4(0.f, 0.f, 0.f, 0.f);
    int k = wid;
    for (; k + 12 < cnt; k += 16) {
        float w0 = s_w[k],      w1 = s_w[k + 4],  w2 = s_w[k + 8],  w3 = s_w[k + 12];
        int   j0 = s_idx[k],    j1 = s_idx[k + 4], j2 = s_idx[k + 8], j3 = s_idx[k + 12];
        float4 x0 = __ldg(&inp4[(size_t)j0 * 32 + lane]);
        float4 x1 = __ldg(&inp4[(size_t)j1 * 32 + lane]);
        float4 x2 = __ldg(&inp4[(size_t)j2 * 32 + lane]);
        float4 x3 = __ldg(&inp4[(size_t)j3 * 32 + lane]);
        acc.x += w0 * x0.x + w1 * x1.x + w2 * x2.x + w3 * x3.x;
        acc.y += w0 * x0.y + w1 * x1.y + w2 * x2.y + w3 * x3.y;
        acc.z += w0 * x0.z + w1 * x1.z + w2 * x2.z + w3 * x3.z;
        acc.w += w0 * x0.w + w1 * x1.w + w2 * x2.w + w3 * x3.w;
    }
    for (; k < cnt; k += 4) {
        float w0 = s_w[k];
        int   j0 = s_idx[k];
        float4 x0 = __ldg(&inp4[(size_t)j0 * 32 + lane]);
        acc.x += w0 * x0.x; acc.y += w0 * x0.y;
        acc.z += w0 * x0.z; acc.w += w0 * x0.w;
    }
    reinterpret_cast<float4*>(s_part)[wid * 32 + lane] = acc;
    __syncthreads();

    float v = (s_part[tid] + s_part[DD + tid] +
               s_part[2 * DD + tid] + s_part[3 * DD + tid]) * inv;
    out[(size_t)row * DD + tid] = v;
}

// ---------------------------------------------------------------------------
extern "C" void kernel_launch(void* const* d_in, const int* in_sizes, int n_in,
                              void* d_out, int out_size)
{
    const float* inputs = (const float*)d_in[0];  // [10000,128]
    const float* adj    = (const float*)d_in[1];  // [10000,10000]
    const float* Hv     = (const float*)d_in[2];  // [128,1]
    float* out          = (float*)d_out;          // [10000,128]

    score_kernel<<<(NN + 3) / 4, 128>>>(inputs, Hv);
    attn_kernel<<<NN, 128>>>(inputs, adj, out);
}

// round 7
// speedup vs baseline: 1.1344x; 1.1344x over previous
#include <cuda_runtime.h>
#include <cstdint>

#define NN 10000
#define DD 128
#define MAXE 256            // max nonzeros/row (mean ~31, extreme tail ~70)
#define CHUNK4 500          // float4 per chunk  (5 * 500 = 2500 = row)
#define CHUNKB (CHUNK4 * 16)  // 8000 bytes
#define NCHUNK 5
#define STAGES 2

__device__ float g_score[NN];

// ---- mbarrier / bulk-async helpers ----------------------------------------
__device__ __forceinline__ uint32_t smem_u32(const void* p) {
    return (uint32_t)__cvta_generic_to_shared(p);
}
__device__ __forceinline__ void mbar_init(uint32_t addr, uint32_t cnt) {
    asm volatile("mbarrier.init.shared.b64 [%0], %1;" :: "r"(addr), "r"(cnt) : "memory");
}
__device__ __forceinline__ void mbar_expect_tx(uint32_t addr, uint32_t bytes) {
    asm volatile("mbarrier.arrive.expect_tx.shared.b64 _, [%0], %1;"
                 :: "r"(addr), "r"(bytes) : "memory");
}
__device__ __forceinline__ void mbar_wait(uint32_t addr, uint32_t parity) {
    asm volatile(
        "{\n\t"
        ".reg .pred P;\n\t"
        "LAB_WAIT%=:\n\t"
        "mbarrier.try_wait.parity.shared.b64 P, [%0], %1;\n\t"
        "@P bra LAB_DONE%=;\n\t"
        "bra LAB_WAIT%=;\n\t"
        "LAB_DONE%=:\n\t"
        "}"
        :: "r"(addr), "r"(parity) : "memory");
}
__device__ __forceinline__ void bulk_g2s(uint32_t dst, const void* src,
                                         uint32_t bytes, uint32_t mbar) {
    asm volatile(
        "cp.async.bulk.shared::cluster.global.mbarrier::complete_tx::bytes "
        "[%0], [%1], %2, [%3];"
        :: "r"(dst), "l"(src), "r"(bytes), "r"(mbar) : "memory");
}

// ---------------------------------------------------------------------------
// Kernel 1: score[j] = dot(inputs[j,:], H_v)   — one warp per row
// ---------------------------------------------------------------------------
__global__ __launch_bounds__(128) void score_kernel(
    const float* __restrict__ inputs, const float* __restrict__ Hv)
{
    int row  = blockIdx.x * (blockDim.x >> 5) + (threadIdx.x >> 5);
    int lane = threadIdx.x & 31;
    if (row >= NN) return;
    const float4* ip = reinterpret_cast<const float4*>(inputs + (size_t)row * DD);
    const float4* hv = reinterpret_cast<const float4*>(Hv);
    float4 a = ip[lane];
    float4 h = hv[lane];
    float acc = a.x * h.x + a.y * h.y + a.z * h.z + a.w * h.w;
    #pragma unroll
    for (int off = 16; off > 0; off >>= 1)
        acc += __shfl_xor_sync(0xffffffffu, acc, off);
    if (lane == 0) g_score[row] = acc;
}

// ---------------------------------------------------------------------------
// Kernel 2: one CTA (128 threads) per row.
// adj row streamed HBM->SMEM by the bulk-async engine (2-stage ring),
// warps scan/compact from SMEM. Latency hiding is engine-side, not reg-side.
// ---------------------------------------------------------------------------
__global__ __launch_bounds__(128) void attn_kernel(
    const float* __restrict__ inputs,
    const float* __restrict__ adj,
    float* __restrict__ out)
{
    __shared__ alignas(16) float4 s_buf[STAGES][CHUNK4];
    __shared__ alignas(16) float  s_w[MAXE];
    __shared__ alignas(16) float  s_part[4 * DD];
    __shared__ int   s_idx[MAXE];
    __shared__ alignas(8) unsigned long long s_bar[STAGES];
    __shared__ int   s_cnt;
    __shared__ float s_red[4];

    const int row  = blockIdx.x;
    const int tid  = threadIdx.x;
    const int wid  = tid >> 5;
    const int lane = tid & 31;

    const uint32_t bar0 = smem_u32(&s_bar[0]);
    const uint32_t bar1 = smem_u32(&s_bar[1]);
    const uint32_t buf0 = smem_u32(&s_buf[0][0]);
    const uint32_t buf1 = smem_u32(&s_buf[1][0]);
    const char* arow = reinterpret_cast<const char*>(adj) + (size_t)row * NN * 4;

    if (tid == 0) {
        s_cnt = 0;
        mbar_init(bar0, 1);
        mbar_init(bar1, 1);
    }
    __syncthreads();

    // Prime the pipeline: chunks 0,1 into stages 0,1
    if (tid == 0) {
        mbar_expect_tx(bar0, CHUNKB);
        bulk_g2s(buf0, arow, CHUNKB, bar0);
        mbar_expect_tx(bar1, CHUNKB);
        bulk_g2s(buf1, arow + CHUNKB, CHUNKB, bar1);
    }

    // ---- Pass 1: chunked scan from SMEM ------------------------------------
    for (int c = 0; c < NCHUNK; c++) {
        const int s = c & 1;
        mbar_wait(s ? bar1 : bar0, (c >> 1) & 1);

        const float4* buf = s_buf[s];
        const int jbase = c * CHUNK4 * 4;
        // 500 float4: thread t handles t, t+128, t+256, t+384(<500)
        #pragma unroll
        for (int u = 0; u < 4; u++) {
            const int v = tid + u * 128;
            if (v < CHUNK4) {
                float4 a = buf[v];
                int j = jbase + (v << 2);
                if (a.x != 0.0f) { int p = atomicAdd(&s_cnt, 1); s_idx[p] = j;     s_w[p] = a.x; }
                if (a.y != 0.0f) { int p = atomicAdd(&s_cnt, 1); s_idx[p] = j + 1; s_w[p] = a.y; }
                if (a.z != 0.0f) { int p = atomicAdd(&s_cnt, 1); s_idx[p] = j + 2; s_w[p] = a.z; }
                if (a.w != 0.0f) { int p = atomicAdd(&s_cnt, 1); s_idx[p] = j + 3; s_w[p] = a.w; }
            }
        }
        __syncthreads();                    // everyone done reading stage s
        if (tid == 0 && c + 2 < NCHUNK) {   // refill stage s with chunk c+2
            uint32_t bar = s ? bar1 : bar0;
            uint32_t dst = s ? buf1 : buf0;
            mbar_expect_tx(bar, CHUNKB);
            bulk_g2s(dst, arow + (size_t)(c + 2) * CHUNKB, CHUNKB, bar);
        }
    }
    const int cnt = s_cnt;   // valid: last loop iteration ended with __syncthreads

    // ---- Pass 2a: logits (parallel score gather) ---------------------------
    for (int k = tid; k < cnt; k += 128)
        s_w[k] = s_w[k] * __ldg(&g_score[s_idx[k]]);
    __syncthreads();

    // ---- Pass 2b: softmax --------------------------------------------------
    float m = -1e30f;
    for (int k = tid; k < cnt; k += 128) m = fmaxf(m, s_w[k]);
    #pragma unroll
    for (int off = 16; off > 0; off >>= 1)
        m = fmaxf(m, __shfl_xor_sync(0xffffffffu, m, off));
    if (lane == 0) s_red[wid] = m;
    __syncthreads();
    m = fmaxf(fmaxf(s_red[0], s_red[1]), fmaxf(s_red[2], s_red[3]));
    __syncthreads();

    float s = 0.0f;
    for (int k = tid; k < cnt; k += 128) {
        float e = __expf(s_w[k] - m);
        s_w[k] = e;
        s += e;
    }
    #pragma unroll
    for (int off = 16; off > 0; off >>= 1)
        s += __shfl_xor_sync(0xffffffffu, s, off);
    if (lane == 0) s_red[wid] = s;
    __syncthreads();
    s = s_red[0] + s_red[1] + s_red[2] + s_red[3];
    const float inv = 1.0f / s;

    // ---- Pass 3: warp-split float4 gather ----------------------------------
    const float4* inp4 = reinterpret_cast<const float4*>(inputs);
    float4 acc = make_float4(0.f, 0.f, 0.f, 0.f);
    int k = wid;
    for (; k + 12 < cnt; k += 16) {
        float w0 = s_w[k],      w1 = s_w[k + 4],  w2 = s_w[k + 8],  w3 = s_w[k + 12];
        int   j0 = s_idx[k],    j1 = s_idx[k + 4], j2 = s_idx[k + 8], j3 = s_idx[k + 12];
        float4 x0 = __ldg(&inp4[(size_t)j0 * 32 + lane]);
        float4 x1 = __ldg(&inp4[(size_t)j1 * 32 + lane]);
        float4 x2 = __ldg(&inp4[(size_t)j2 * 32 + lane]);
        float4 x3 = __ldg(&inp4[(size_t)j3 * 32 + lane]);
        acc.x += w0 * x0.x + w1 * x1.x + w2 * x2.x + w3 * x3.x;
        acc.y += w0 * x0.y + w1 * x1.y + w2 * x2.y + w3 * x3.y;
        acc.z += w0 * x0.z + w1 * x1.z + w2 * x2.z + w3 * x3.z;
        acc.w += w0 * x0.w + w1 * x1.w + w2 * x2.w + w3 * x3.w;
    }
    for (; k < cnt; k += 4) {
        float w0 = s_w[k];
        int   j0 = s_idx[k];
        float4 x0 = __ldg(&inp4[(size_t)j0 * 32 + lane]);
        acc.x += w0 * x0.x; acc.y += w0 * x0.y;
        acc.z += w0 * x0.z; acc.w += w0 * x0.w;
    }
    reinterpret_cast<float4*>(s_part)[wid * 32 + lane] = acc;
    __syncthreads();

    float v = (s_part[tid] + s_part[DD + tid] +
               s_part[2 * DD + tid] + s_part[3 * DD + tid]) * inv;
    out[(size_t)row * DD + tid] = v;
}

// ---------------------------------------------------------------------------
extern "C" void kernel_launch(void* const* d_in, const int* in_sizes, int n_in,
                              void* d_out, int out_size)
{
    const float* inputs = (const float*)d_in[0];  // [10000,128]
    const float* adj    = (const float*)d_in[1];  // [10000,10000]
    const float* Hv     = (const float*)d_in[2];  // [128,1]
    float* out          = (float*)d_out;          // [10000,128]

    score_kernel<<<(NN + 3) / 4, 128>>>(inputs, Hv);
    attn_kernel<<<NN, 128>>>(inputs, adj, out);
}